// round 11
// baseline (speedup 1.0000x reference)
#include <cuda_runtime.h>
#include <stdint.h>

// out[b,c, i*64+a, j*64+d] = x[b,c, i'*64+a, j'*64+d] + pos[c*64 + p']
//   p = i*8+j ; p' = (p+c) & 63 ; i' = p'>>3 ; j' = p'&7
//
// Shapes: B=8, C=64, H=W=512, PH=PW=8, kh=kw=64, PN=64.
// Total float4 elements: 8*64*512*128 = 33,554,432.
//
// Persistent grid-stride version: ~one wave of CTAs (1216 = 152 SM * occ 8),
// each looping over tiles. Removes ~27 wave transitions / drain bubbles.
// Per iteration each thread handles 4 float4 chunks, loads front-batched
// (MLP=4), streaming cache hints on both bulk streams.

#define TOTAL_F4 33554432u
#define TPB      256u
#define CHUNKS   4u
#define TILE_F4  (TPB * CHUNKS)            // 1024 float4 per tile
#define NTILES   (TOTAL_F4 / TILE_F4)      // 32768 tiles
#define GRID     1216u                     // 152 SMs * 8 CTAs (ok on 148 too)

__global__ __launch_bounds__(TPB)
void cross_patch_kernel(const float4* __restrict__ x4,
                        const float* __restrict__ pos,
                        float4* __restrict__ out4)
{
    for (uint32_t tile = blockIdx.x; tile < NTILES; tile += GRID) {
        uint32_t base = tile * TILE_F4 + threadIdx.x;

        uint32_t dst[CHUNKS];
        uint32_t src[CHUNKS];
        float    bias[CHUNKS];

        #pragma unroll
        for (uint32_t k = 0; k < CHUNKS; k++) {
            uint32_t idx = base + k * TPB;     // float4 index into output
            uint32_t gx4 = idx & 127u;         // float4 col (W/4 = 128)
            uint32_t gy  = (idx >> 7) & 511u;  // row
            uint32_t c   = (idx >> 16) & 63u;  // channel

            uint32_t i   = gy >> 6;            // patch row
            uint32_t a   = gy & 63u;           // row within patch
            uint32_t j   = gx4 >> 4;           // patch col
            uint32_t dx4 = gx4 & 15u;          // float4 within patch col

            uint32_t p  = (i << 3) | j;
            uint32_t pp = (p + c) & 63u;       // source patch
            uint32_t ip = pp >> 3;
            uint32_t jp = pp & 7u;

            uint32_t plane = (idx >> 16) << 16;   // (b*64+c)*512*128
            dst[k]  = idx;
            src[k]  = plane + (((ip << 6) | a) << 7) + (jp << 4) + dx4;
            bias[k] = __ldg(&pos[(c << 6) | pp]); // tiny 16KB table: stays cached
        }

        // Front-batch the 4 independent 16B loads (MLP=4 per thread).
        float4 v[CHUNKS];
        #pragma unroll
        for (uint32_t k = 0; k < CHUNKS; k++)
            v[k] = __ldcs(&x4[src[k]]);

        #pragma unroll
        for (uint32_t k = 0; k < CHUNKS; k++) {
            float4 r = v[k];
            float  s = bias[k];
            r.x += s; r.y += s; r.z += s; r.w += s;
            __stcs(&out4[dst[k]], r);
        }
    }
}

extern "C" void kernel_launch(void* const* d_in, const int* in_sizes, int n_in,
                              void* d_out, int out_size)
{
    const float4* x4  = (const float4*)d_in[0];   // x: [8,64,512,512] f32
    const float*  pos = (const float*)d_in[1];    // abs_pos -> [c, p] table (64x64)
    float4* out4 = (float4*)d_out;

    (void)in_sizes; (void)n_in; (void)out_size;

    cross_patch_kernel<<<GRID, TPB>>>(x4, pos, out4);
}

// round 12
// speedup vs baseline: 1.1287x; 1.1287x over previous
#include <cuda_runtime.h>
#include <stdint.h>

// out[b,c, i*64+a, j*64+d] = x[b,c, i'*64+a, j'*64+d] + pos[c*64 + p']
//   p = i*8+j ; p' = (p+c) & 63 ; i' = p'>>3 ; j' = p'&7
//
// Shapes: B=8, C=64, H=W=512, PH=PW=8, kh=kw=64, PN=64.
// Total float4 elements: 8*64*512*128 = 33,554,432.
//
// Non-persistent (R10 shape — persistent loop regressed). Each thread
// handles 8 float4 chunks spaced by blockDim, loads front-batched (MLP=8),
// streaming cache hints on both bulk streams. 16384 CTAs.

#define TOTAL_F4 33554432u
#define TPB      256u
#define CHUNKS   8u

__global__ __launch_bounds__(TPB)
void cross_patch_kernel(const float4* __restrict__ x4,
                        const float* __restrict__ pos,
                        float4* __restrict__ out4)
{
    uint32_t base = blockIdx.x * (TPB * CHUNKS) + threadIdx.x;

    uint32_t dst[CHUNKS];
    uint32_t src[CHUNKS];
    float    bias[CHUNKS];

    #pragma unroll
    for (uint32_t k = 0; k < CHUNKS; k++) {
        uint32_t idx = base + k * TPB;     // float4 index into output
        uint32_t gx4 = idx & 127u;         // float4 col (W/4 = 128)
        uint32_t gy  = (idx >> 7) & 511u;  // row
        uint32_t c   = (idx >> 16) & 63u;  // channel

        uint32_t i   = gy >> 6;            // patch row
        uint32_t a   = gy & 63u;           // row within patch
        uint32_t j   = gx4 >> 4;           // patch col
        uint32_t dx4 = gx4 & 15u;          // float4 within patch col

        uint32_t p  = (i << 3) | j;
        uint32_t pp = (p + c) & 63u;       // source patch
        uint32_t ip = pp >> 3;
        uint32_t jp = pp & 7u;

        uint32_t plane = (idx >> 16) << 16;   // (b*64+c)*512*128
        dst[k]  = idx;
        src[k]  = plane + (((ip << 6) | a) << 7) + (jp << 4) + dx4;
        bias[k] = __ldg(&pos[(c << 6) | pp]); // tiny 16KB table: stays cached
    }

    // Front-batch the 8 independent 16B loads (MLP=8 per thread).
    float4 v[CHUNKS];
    #pragma unroll
    for (uint32_t k = 0; k < CHUNKS; k++)
        v[k] = __ldcs(&x4[src[k]]);

    #pragma unroll
    for (uint32_t k = 0; k < CHUNKS; k++) {
        float4 r = v[k];
        float  s = bias[k];
        r.x += s; r.y += s; r.z += s; r.w += s;
        __stcs(&out4[dst[k]], r);
    }
}

extern "C" void kernel_launch(void* const* d_in, const int* in_sizes, int n_in,
                              void* d_out, int out_size)
{
    const float4* x4  = (const float4*)d_in[0];   // x: [8,64,512,512] f32
    const float*  pos = (const float*)d_in[1];    // abs_pos -> [c, p] table (64x64)
    float4* out4 = (float4*)d_out;

    (void)in_sizes; (void)n_in; (void)out_size;

    dim3 grid(TOTAL_F4 / (TPB * CHUNKS));         // 16384 blocks
    cross_patch_kernel<<<grid, TPB>>>(x4, pos, out4);
}

// round 13
// speedup vs baseline: 1.1308x; 1.0018x over previous
#include <cuda_runtime.h>
#include <stdint.h>

// out[b,c, i*64+a, j*64+d] = x[b,c, i'*64+a, j'*64+d] + pos[c*64 + p']
//   p = i*8+j ; p' = (p+c) & 63 ; i' = p'>>3 ; j' = p'&7
//
// Shapes: B=8, C=64, H=W=512, PH=PW=8, kh=kw=64, PN=64.
// Total float4 elements: 8*64*512*128 = 33,554,432.
//
// Best-known mechanism set (R10): non-persistent, per-thread MLP=4
// front-batched LDG.128, streaming hints both sides. This round: finer
// CTA granularity (TPB 128, 65536 CTAs) for smoother work-steal
// interleave / smaller tail quantum; everything else identical.

#define TOTAL_F4 33554432u
#define TPB      128u
#define CHUNKS   4u

__global__ __launch_bounds__(TPB)
void cross_patch_kernel(const float4* __restrict__ x4,
                        const float* __restrict__ pos,
                        float4* __restrict__ out4)
{
    uint32_t base = blockIdx.x * (TPB * CHUNKS) + threadIdx.x;

    uint32_t dst[CHUNKS];
    uint32_t src[CHUNKS];
    float    bias[CHUNKS];

    #pragma unroll
    for (uint32_t k = 0; k < CHUNKS; k++) {
        uint32_t idx = base + k * TPB;     // float4 index into output
        uint32_t gx4 = idx & 127u;         // float4 col (W/4 = 128)
        uint32_t gy  = (idx >> 7) & 511u;  // row
        uint32_t c   = (idx >> 16) & 63u;  // channel

        uint32_t i   = gy >> 6;            // patch row
        uint32_t a   = gy & 63u;           // row within patch
        uint32_t j   = gx4 >> 4;           // patch col
        uint32_t dx4 = gx4 & 15u;          // float4 within patch col

        uint32_t p  = (i << 3) | j;
        uint32_t pp = (p + c) & 63u;       // source patch
        uint32_t ip = pp >> 3;
        uint32_t jp = pp & 7u;

        uint32_t plane = (idx >> 16) << 16;   // (b*64+c)*512*128
        dst[k]  = idx;
        src[k]  = plane + (((ip << 6) | a) << 7) + (jp << 4) + dx4;
        bias[k] = __ldg(&pos[(c << 6) | pp]); // tiny 16KB table: stays cached
    }

    // Front-batch the 4 independent 16B loads (MLP=4 per thread).
    float4 v[CHUNKS];
    #pragma unroll
    for (uint32_t k = 0; k < CHUNKS; k++)
        v[k] = __ldcs(&x4[src[k]]);

    #pragma unroll
    for (uint32_t k = 0; k < CHUNKS; k++) {
        float4 r = v[k];
        float  s = bias[k];
        r.x += s; r.y += s; r.z += s; r.w += s;
        __stcs(&out4[dst[k]], r);
    }
}

extern "C" void kernel_launch(void* const* d_in, const int* in_sizes, int n_in,
                              void* d_out, int out_size)
{
    const float4* x4  = (const float4*)d_in[0];   // x: [8,64,512,512] f32
    const float*  pos = (const float*)d_in[1];    // abs_pos -> [c, p] table (64x64)
    float4* out4 = (float4*)d_out;

    (void)in_sizes; (void)n_in; (void)out_size;

    dim3 grid(TOTAL_F4 / (TPB * CHUNKS));         // 65536 blocks
    cross_patch_kernel<<<grid, TPB>>>(x4, pos, out4);
}